// round 15
// baseline (speedup 1.0000x reference)
#include <cuda_runtime.h>
#include <cuda_bf16.h>
#include <cstdint>
#include <math.h>

#define NTOK   4096
#define DMODEL 256
#define NHEAD  8
#define HDIM   32
#define QKVDIM (3 * DMODEL)   // 768

// ---------------------------------------------------------------------------
// Scratch (allocation-free rule: __device__ globals)
// ---------------------------------------------------------------------------
__device__ __align__(16) float g_qkv[NTOK * QKVDIM];    // fp32 QKV
__device__ __align__(16) float g_delta[NTOK * DMODEL];  // projected delta
// precomputed bf16 hi/lo operands
__device__ __align__(16) __nv_bfloat16 g_xh[NTOK * DMODEL];
__device__ __align__(16) __nv_bfloat16 g_xl[NTOK * DMODEL];
__device__ __align__(16) __nv_bfloat16 g_wih[QKVDIM * DMODEL];
__device__ __align__(16) __nv_bfloat16 g_wil[QKVDIM * DMODEL];
__device__ __align__(16) __nv_bfloat16 g_woh[DMODEL * DMODEL];
__device__ __align__(16) __nv_bfloat16 g_wol[DMODEL * DMODEL];
__device__ __align__(16) __nv_bfloat16 g_ah[NTOK * DMODEL];   // attn out hi
__device__ __align__(16) __nv_bfloat16 g_al[NTOK * DMODEL];   // attn out lo

// ---------------------------------------------------------------------------
// fp32 -> (bf16 hi, bf16 lo) split. 4 floats / thread.
// ---------------------------------------------------------------------------
__global__ __launch_bounds__(256) void split_bf16_kernel(
    const float* __restrict__ in, __nv_bfloat16* __restrict__ hi,
    __nv_bfloat16* __restrict__ lo, int n4)
{
    int i = blockIdx.x * blockDim.x + threadIdx.x;
    if (i >= n4) return;
    float4 v = ((const float4*)in)[i];
    __nv_bfloat16 h0 = __float2bfloat16(v.x), h1 = __float2bfloat16(v.y);
    __nv_bfloat16 h2 = __float2bfloat16(v.z), h3 = __float2bfloat16(v.w);
    __nv_bfloat16 l0 = __float2bfloat16(v.x - __bfloat162float(h0));
    __nv_bfloat16 l1 = __float2bfloat16(v.y - __bfloat162float(h1));
    __nv_bfloat16 l2 = __float2bfloat16(v.z - __bfloat162float(h2));
    __nv_bfloat16 l3 = __float2bfloat16(v.w - __bfloat162float(h3));
    __nv_bfloat162 hp0(h0, h1), hp1(h2, h3), lp0(l0, l1), lp1(l2, l3);
    uint2 hv, lv;
    hv.x = *(uint32_t*)&hp0; hv.y = *(uint32_t*)&hp1;
    lv.x = *(uint32_t*)&lp0; lv.y = *(uint32_t*)&lp1;
    ((uint2*)hi)[i] = hv;
    ((uint2*)lo)[i] = lv;
}

// ---------------------------------------------------------------------------
// GEMM v4: C[M,Nc] = A[M,256] @ B[Nc,256]^T + bias, operands pre-split bf16
// hi/lo (3 HMMA passes AhBh+AhBl+AlBh, fp32 accum). BM=128, BN=64, BK=64,
// cp.async 2-stage pipeline. 256 threads, 8 warps, warp tile 32x32.
// Row stride 144 B = 16*9: cp.async 16B endpoints aligned; 144/4 = 36 ≡ 4
// (mod 32) keeps fragment LDS conflict-free.
// ---------------------------------------------------------------------------
#define SA_ROWB 144
#define ST_AH   0
#define ST_AL   (ST_AH + 128 * SA_ROWB)   // 18432
#define ST_BH   (ST_AL + 128 * SA_ROWB)   // 36864
#define ST_BL   (ST_BH + 64 * SA_ROWB)    // 46080
#define STAGEB  (ST_BL + 64 * SA_ROWB)    // 55296 per stage
#define GM_SMEM (2 * STAGEB)              // 110592 total

__device__ __forceinline__ void mma_bf16(float* c, const uint32_t* a, const uint32_t* b)
{
    asm volatile(
        "mma.sync.aligned.m16n8k16.row.col.f32.bf16.bf16.f32 "
        "{%0,%1,%2,%3}, {%4,%5,%6,%7}, {%8,%9}, {%0,%1,%2,%3};"
        : "+f"(c[0]), "+f"(c[1]), "+f"(c[2]), "+f"(c[3])
        : "r"(a[0]), "r"(a[1]), "r"(a[2]), "r"(a[3]), "r"(b[0]), "r"(b[1]));
}

__device__ __forceinline__ void cpa16(uint32_t s, const void* g)
{
    asm volatile("cp.async.cg.shared.global [%0], [%1], 16;"
                 :: "r"(s), "l"(g) : "memory");
}

__global__ __launch_bounds__(256, 2) void mma_gemm_kernel(
    const __nv_bfloat16* __restrict__ Ah, const __nv_bfloat16* __restrict__ Al,
    const __nv_bfloat16* __restrict__ Bh, const __nv_bfloat16* __restrict__ Bl,
    const float* __restrict__ bias, float* __restrict__ C, int Nc)
{
    extern __shared__ __align__(16) char sm[];
    const uint32_t sbase = (uint32_t)__cvta_generic_to_shared(sm);
    const int tid  = threadIdx.x;
    const int wid  = tid >> 5;
    const int lane = tid & 31;
    const int g    = lane >> 2;      // 0..7
    const int t4   = lane & 3;       // 0..3
    const int row0 = blockIdx.y * 128;
    const int col0 = blockIdx.x * 64;
    const int wm   = (wid & 3) * 32;
    const int wn   = (wid >> 2) * 32;

    // issue all cp.async for one 64-wide K chunk into stage stg
    auto load_chunk = [&](int it, int stg) {
        const uint32_t sb = sbase + stg * STAGEB;
        const int kb = it * 64;
#pragma unroll
        for (int i = 0; i < 4; i++) {          // A: 1024 pairs, 4/thread
            int p = tid + (i << 8);
            int r = p >> 3, q = p & 7;
            size_t go = (size_t)(row0 + r) * 256 + kb + q * 8;
            uint32_t so = r * SA_ROWB + q * 16;
            cpa16(sb + ST_AH + so, Ah + go);
            cpa16(sb + ST_AL + so, Al + go);
        }
#pragma unroll
        for (int i = 0; i < 2; i++) {          // B: 512 pairs, 2/thread
            int p = tid + (i << 8);
            int r = p >> 3, q = p & 7;
            size_t go = (size_t)(col0 + r) * 256 + kb + q * 8;
            uint32_t so = r * SA_ROWB + q * 16;
            cpa16(sb + ST_BH + so, Bh + go);
            cpa16(sb + ST_BL + so, Bl + go);
        }
        asm volatile("cp.async.commit_group;" ::: "memory");
    };

    float acc[2][4][4];
#pragma unroll
    for (int mi = 0; mi < 2; mi++)
#pragma unroll
        for (int ni = 0; ni < 4; ni++)
#pragma unroll
            for (int k = 0; k < 4; k++) acc[mi][ni][k] = 0.f;

    const uint32_t a_row = (uint32_t)(wm + g);
    const uint32_t b_row = (uint32_t)(wn + g);
    const uint32_t kb0   = (uint32_t)(t4 * 4);

    load_chunk(0, 0);                 // prologue

#pragma unroll
    for (int it = 0; it < 4; it++) {
        if (it < 3) load_chunk(it + 1, (it + 1) & 1);
        if (it < 3) asm volatile("cp.async.wait_group 1;" ::: "memory");
        else        asm volatile("cp.async.wait_group 0;" ::: "memory");
        __syncthreads();              // chunk `it` resident for all warps

        const char* s = sm + (it & 1) * STAGEB;
#pragma unroll
        for (int p = 0; p < 3; p++) {
            const char* Ab = s + ((p == 2) ? ST_AL : ST_AH);
            const char* Bb = s + ((p == 1) ? ST_BL : ST_BH);
#pragma unroll
            for (int st = 0; st < 4; st++) {
                const uint32_t kf = (uint32_t)(st * 32) + kb0;
                uint32_t af[2][4], bf[4][2];
#pragma unroll
                for (int mi = 0; mi < 2; mi++) {
                    const char* ap = Ab + (a_row + mi * 16) * SA_ROWB + kf;
                    af[mi][0] = *(const uint32_t*)(ap);
                    af[mi][1] = *(const uint32_t*)(ap + 8 * SA_ROWB);
                    af[mi][2] = *(const uint32_t*)(ap + 16);
                    af[mi][3] = *(const uint32_t*)(ap + 8 * SA_ROWB + 16);
                }
#pragma unroll
                for (int ni = 0; ni < 4; ni++) {
                    const char* bp = Bb + (b_row + ni * 8) * SA_ROWB + kf;
                    bf[ni][0] = *(const uint32_t*)(bp);
                    bf[ni][1] = *(const uint32_t*)(bp + 16);
                }
#pragma unroll
                for (int mi = 0; mi < 2; mi++)
#pragma unroll
                    for (int ni = 0; ni < 4; ni++)
                        mma_bf16(acc[mi][ni], af[mi], bf[ni]);
            }
        }
        __syncthreads();  // reads done before this stage is refilled (it+2)
    }

    // --- Epilogue: add bias, store fp32 ---
#pragma unroll
    for (int mi = 0; mi < 2; mi++) {
        const int r0 = row0 + wm + mi * 16 + g;
#pragma unroll
        for (int ni = 0; ni < 4; ni++) {
            const int col = col0 + wn + ni * 8 + t4 * 2;
            const float bx = bias[col], by = bias[col + 1];
            float2 v0 = make_float2(acc[mi][ni][0] + bx, acc[mi][ni][1] + by);
            float2 v1 = make_float2(acc[mi][ni][2] + bx, acc[mi][ni][3] + by);
            *(float2*)(C + (size_t)r0 * Nc + col)       = v0;
            *(float2*)(C + (size_t)(r0 + 8) * Nc + col) = v1;
        }
    }
}

// ---------------------------------------------------------------------------
// Block-diagonal flash attention v2 (numerics unchanged from R14); epilogue
// now writes bf16 hi/lo directly (feeds the proj GEMM, kills a split pass).
// ---------------------------------------------------------------------------
__device__ __forceinline__ int lb_search(const int* __restrict__ a, int n, int v)
{
    int lo = 0, hi = n;
    while (lo < hi) {
        int mid = (lo + hi) >> 1;
        if (a[mid] < v) lo = mid + 1; else hi = mid;
    }
    return lo;
}

__global__ __launch_bounds__(128) void attn_kernel(
    const float* __restrict__ qkv, const int* __restrict__ bidx,
    __nv_bfloat16* __restrict__ oh, __nv_bfloat16* __restrict__ ol)
{
    __shared__ __align__(16) float Ks[64][32];
    __shared__ __align__(16) float Vs[64][32];
    __shared__ int sh_range[2];

    const int h   = blockIdx.y;
    const int tid = threadIdx.x;
    const int n   = blockIdx.x * 128 + tid;

    const int b = bidx[n];
    const int s = lb_search(bidx, NTOK, b);
    const int e = lb_search(bidx, NTOK, b + 1);
    if (tid == 0)   sh_range[0] = s;
    if (tid == 127) sh_range[1] = e;

    const float scale = 0.1767766952966368811f;  // 1/sqrt(32)
    float4 qv[8];
    {
        const float* qp = qkv + (size_t)n * QKVDIM + h * HDIM;
#pragma unroll
        for (int i = 0; i < 8; i++) {
            float4 v = *(const float4*)(qp + i * 4);
            qv[i] = make_float4(v.x * scale, v.y * scale, v.z * scale, v.w * scale);
        }
    }

    float4 ov[8];
#pragma unroll
    for (int i = 0; i < 8; i++) ov[i] = make_float4(0.f, 0.f, 0.f, 0.f);
    float m = -1e30f, l = 0.f;

    __syncthreads();
    const int smin = sh_range[0];
    const int emax = sh_range[1];

    for (int kt = smin; kt < emax; kt += 64) {
#pragma unroll
        for (int i = 0; i < 4; i++) {
            int idx = tid + (i << 7);
            int r   = idx >> 3;
            int d4  = idx & 7;
            int kr  = kt + r;
            if (kr < NTOK) {
                const float* kp = qkv + (size_t)kr * QKVDIM + DMODEL + h * HDIM + (d4 << 2);
                *(float4*)&Ks[r][d4 << 2] = *(const float4*)kp;
                *(float4*)&Vs[r][d4 << 2] = *(const float4*)(kp + DMODEL);
            }
        }
        __syncthreads();

        int jlo = s - kt; if (jlo < 0)  jlo = 0;
        int jhi = e - kt; if (jhi > 64) jhi = 64;
        int j = jlo;
        for (; j + 1 < jhi; j += 2) {
            const float4* k0 = (const float4*)Ks[j];
            const float4* k1 = (const float4*)Ks[j + 1];
            float s00 = 0.f, s01 = 0.f, s02 = 0.f, s03 = 0.f;
            float s10 = 0.f, s11 = 0.f, s12 = 0.f, s13 = 0.f;
#pragma unroll
            for (int i = 0; i < 8; i++) {
                float4 a = qv[i], b0 = k0[i], b1 = k1[i];
                s00 += a.x * b0.x; s01 += a.y * b0.y;
                s02 += a.z * b0.z; s03 += a.w * b0.w;
                s10 += a.x * b1.x; s11 += a.y * b1.y;
                s12 += a.z * b1.z; s13 += a.w * b1.w;
            }
            float sc0 = (s00 + s01) + (s02 + s03);
            float sc1 = (s10 + s11) + (s12 + s13);
            float mn = fmaxf(m, fmaxf(sc0, sc1));
            if (mn > m) {
                float corr = __expf(m - mn);
                l *= corr;
#pragma unroll
                for (int i = 0; i < 8; i++) {
                    ov[i].x *= corr; ov[i].y *= corr;
                    ov[i].z *= corr; ov[i].w *= corr;
                }
                m = mn;
            }
            float p0 = __expf(sc0 - m);
            float p1 = __expf(sc1 - m);
            l += p0 + p1;
            const float4* v0 = (const float4*)Vs[j];
            const float4* v1 = (const float4*)Vs[j + 1];
#pragma unroll
            for (int i = 0; i < 8; i++) {
                float4 a = v0[i], c = v1[i];
                ov[i].x += p0 * a.x + p1 * c.x;
                ov[i].y += p0 * a.y + p1 * c.y;
                ov[i].z += p0 * a.z + p1 * c.z;
                ov[i].w += p0 * a.w + p1 * c.w;
            }
        }
        if (j < jhi) {
            const float4* k0 = (const float4*)Ks[j];
            float s00 = 0.f, s01 = 0.f, s02 = 0.f, s03 = 0.f;
#pragma unroll
            for (int i = 0; i < 8; i++) {
                float4 a = qv[i], b0 = k0[i];
                s00 += a.x * b0.x; s01 += a.y * b0.y;
                s02 += a.z * b0.z; s03 += a.w * b0.w;
            }
            float sc0 = (s00 + s01) + (s02 + s03);
            if (sc0 > m) {
                float corr = __expf(m - sc0);
                l *= corr;
#pragma unroll
                for (int i = 0; i < 8; i++) {
                    ov[i].x *= corr; ov[i].y *= corr;
                    ov[i].z *= corr; ov[i].w *= corr;
                }
                m = sc0;
            }
            float p0 = __expf(sc0 - m);
            l += p0;
            const float4* v0 = (const float4*)Vs[j];
#pragma unroll
            for (int i = 0; i < 8; i++) {
                float4 a = v0[i];
                ov[i].x += p0 * a.x; ov[i].y += p0 * a.y;
                ov[i].z += p0 * a.z; ov[i].w += p0 * a.w;
            }
        }
        __syncthreads();
    }

    // epilogue: normalize + split to bf16 hi/lo
    const float inv = 1.f / l;
    const size_t ob = (size_t)n * DMODEL + h * HDIM;
#pragma unroll
    for (int i = 0; i < 8; i++) {
        float x0 = ov[i].x * inv, x1 = ov[i].y * inv;
        float x2 = ov[i].z * inv, x3 = ov[i].w * inv;
        __nv_bfloat16 h0 = __float2bfloat16(x0), h1 = __float2bfloat16(x1);
        __nv_bfloat16 h2 = __float2bfloat16(x2), h3 = __float2bfloat16(x3);
        __nv_bfloat16 l0 = __float2bfloat16(x0 - __bfloat162float(h0));
        __nv_bfloat16 l1 = __float2bfloat16(x1 - __bfloat162float(h1));
        __nv_bfloat16 l2 = __float2bfloat16(x2 - __bfloat162float(h2));
        __nv_bfloat16 l3 = __float2bfloat16(x3 - __bfloat162float(h3));
        __nv_bfloat162 hp0(h0, h1), hp1(h2, h3), lp0(l0, l1), lp1(l2, l3);
        uint2 hv, lv;
        hv.x = *(uint32_t*)&hp0; hv.y = *(uint32_t*)&hp1;
        lv.x = *(uint32_t*)&lp0; lv.y = *(uint32_t*)&lp1;
        *(uint2*)(oh + ob + i * 4) = hv;
        *(uint2*)(ol + ob + i * 4) = lv;
    }
}

// ---------------------------------------------------------------------------
// Fused residual + LayerNorm. Warp per row.
// ---------------------------------------------------------------------------
__global__ __launch_bounds__(256) void ln_kernel(
    const float* __restrict__ x, const float* __restrict__ delta,
    const float* __restrict__ gamma, const float* __restrict__ beta,
    float* __restrict__ out)
{
    const int row  = blockIdx.x * 8 + (threadIdx.x >> 5);
    const int lane = threadIdx.x & 31;

    const float4* xp = (const float4*)(x + (size_t)row * DMODEL);
    const float4* dp = (const float4*)(delta + (size_t)row * DMODEL);

    float4 a = xp[lane],      bb = dp[lane];
    float4 v0 = make_float4(a.x + bb.x, a.y + bb.y, a.z + bb.z, a.w + bb.w);
    a = xp[lane + 32]; bb = dp[lane + 32];
    float4 v1 = make_float4(a.x + bb.x, a.y + bb.y, a.z + bb.z, a.w + bb.w);

    float sum = v0.x + v0.y + v0.z + v0.w + v1.x + v1.y + v1.z + v1.w;
#pragma unroll
    for (int off = 16; off; off >>= 1) sum += __shfl_xor_sync(0xffffffffu, sum, off);
    const float mean = sum * (1.f / 256.f);

    float sq = (v0.x - mean) * (v0.x - mean) + (v0.y - mean) * (v0.y - mean)
             + (v0.z - mean) * (v0.z - mean) + (v0.w - mean) * (v0.w - mean)
             + (v1.x - mean) * (v1.x - mean) + (v1.y - mean) * (v1.y - mean)
             + (v1.z - mean) * (v1.z - mean) + (v1.w - mean) * (v1.w - mean);
#pragma unroll
    for (int off = 16; off; off >>= 1) sq += __shfl_xor_sync(0xffffffffu, sq, off);
    const float rstd = rsqrtf(sq * (1.f / 256.f) + 1e-5f);

    float4 g = ((const float4*)gamma)[lane];
    float4 bt = ((const float4*)beta)[lane];
    float4 r0;
    r0.x = (v0.x - mean) * rstd * g.x + bt.x;
    r0.y = (v0.y - mean) * rstd * g.y + bt.y;
    r0.z = (v0.z - mean) * rstd * g.z + bt.z;
    r0.w = (v0.w - mean) * rstd * g.w + bt.w;
    g  = ((const float4*)gamma)[lane + 32];
    bt = ((const float4*)beta)[lane + 32];
    float4 r1;
    r1.x = (v1.x - mean) * rstd * g.x + bt.x;
    r1.y = (v1.y - mean) * rstd * g.y + bt.y;
    r1.z = (v1.z - mean) * rstd * g.z + bt.z;
    r1.w = (v1.w - mean) * rstd * g.w + bt.w;

    float4* op = (float4*)(out + (size_t)row * DMODEL);
    op[lane]      = r0;
    op[lane + 32] = r1;
}

// ---------------------------------------------------------------------------
// Launch (graph-capturable: kernel launches on default stream only)
// ---------------------------------------------------------------------------
extern "C" void kernel_launch(void* const* d_in, const int* in_sizes, int n_in,
                              void* d_out, int out_size)
{
    const float* slots  = (const float*)d_in[0];   // [1, 4096, 256]
    const int*   bidx   = (const int*)  d_in[1];   // [4096] sorted
    const float* w_in   = (const float*)d_in[2];   // [768, 256]
    const float* b_in   = (const float*)d_in[3];   // [768]
    const float* w_out  = (const float*)d_in[4];   // [256, 256]
    const float* b_out  = (const float*)d_in[5];   // [256]
    const float* ln_g   = (const float*)d_in[6];   // [256]
    const float* ln_b   = (const float*)d_in[7];   // [256]
    float*       out    = (float*)d_out;           // [1, 4096, 256]

    float *qkv, *delta;
    __nv_bfloat16 *xh, *xl, *wih, *wil, *woh, *wol, *ah, *al;
    cudaGetSymbolAddress((void**)&qkv,   g_qkv);
    cudaGetSymbolAddress((void**)&delta, g_delta);
    cudaGetSymbolAddress((void**)&xh,  g_xh);
    cudaGetSymbolAddress((void**)&xl,  g_xl);
    cudaGetSymbolAddress((void**)&wih, g_wih);
    cudaGetSymbolAddress((void**)&wil, g_wil);
    cudaGetSymbolAddress((void**)&woh, g_woh);
    cudaGetSymbolAddress((void**)&wol, g_wol);
    cudaGetSymbolAddress((void**)&ah,  g_ah);
    cudaGetSymbolAddress((void**)&al,  g_al);

    cudaFuncSetAttribute(mma_gemm_kernel,
                         cudaFuncAttributeMaxDynamicSharedMemorySize, GM_SMEM);

    // 0) one-time fp32 -> bf16 hi/lo splits
    split_bf16_kernel<<<NTOK * DMODEL / 4 / 256, 256>>>(slots, xh, xl, NTOK * DMODEL / 4);
    split_bf16_kernel<<<QKVDIM * DMODEL / 4 / 256, 256>>>(w_in, wih, wil, QKVDIM * DMODEL / 4);
    split_bf16_kernel<<<DMODEL * DMODEL / 4 / 256, 256>>>(w_out, woh, wol, DMODEL * DMODEL / 4);

    // 1) QKV = x @ w_in^T + b_in   [4096, 768]
    {
        dim3 grid(QKVDIM / 64, NTOK / 128);
        mma_gemm_kernel<<<grid, 256, GM_SMEM>>>(xh, xl, wih, wil, b_in, qkv, QKVDIM);
    }
    // 2) Block-diagonal attention -> bf16 hi/lo   [4096, 256]
    {
        dim3 grid(NTOK / 128, NHEAD);
        attn_kernel<<<grid, 128>>>(qkv, bidx, ah, al);
    }
    // 3) delta = attn @ w_out^T + b_out   [4096, 256]
    {
        dim3 grid(DMODEL / 64, NTOK / 128);
        mma_gemm_kernel<<<grid, 256, GM_SMEM>>>(ah, al, woh, wol, b_out, delta, DMODEL);
    }
    // 4) out = LayerNorm(x + delta)
    ln_kernel<<<NTOK / 8, 256>>>(slots, delta, ln_g, ln_b, out);
}

// round 16
// speedup vs baseline: 1.5817x; 1.5817x over previous
#include <cuda_runtime.h>
#include <cuda_bf16.h>
#include <cstdint>
#include <math.h>

#define NTOK   4096
#define DMODEL 256
#define NHEAD  8
#define HDIM   32
#define QKVDIM (3 * DMODEL)   // 768

// ---------------------------------------------------------------------------
// Scratch (allocation-free rule: __device__ globals)
// ---------------------------------------------------------------------------
__device__ __align__(16) float g_qkv[NTOK * QKVDIM];    // fp32 QKV
__device__ __align__(16) float g_delta[NTOK * DMODEL];  // projected delta
__device__ __align__(16) __nv_bfloat16 g_xh[NTOK * DMODEL];
__device__ __align__(16) __nv_bfloat16 g_xl[NTOK * DMODEL];
__device__ __align__(16) __nv_bfloat16 g_wih[QKVDIM * DMODEL];
__device__ __align__(16) __nv_bfloat16 g_wil[QKVDIM * DMODEL];
__device__ __align__(16) __nv_bfloat16 g_woh[DMODEL * DMODEL];
__device__ __align__(16) __nv_bfloat16 g_wol[DMODEL * DMODEL];
__device__ __align__(16) __nv_bfloat16 g_ah[NTOK * DMODEL];   // attn out hi
__device__ __align__(16) __nv_bfloat16 g_al[NTOK * DMODEL];   // attn out lo

// ---------------------------------------------------------------------------
// fp32 -> (bf16 hi, bf16 lo) split. 4 floats / thread.
// ---------------------------------------------------------------------------
__global__ __launch_bounds__(256) void split_bf16_kernel(
    const float* __restrict__ in, __nv_bfloat16* __restrict__ hi,
    __nv_bfloat16* __restrict__ lo, int n4)
{
    int i = blockIdx.x * blockDim.x + threadIdx.x;
    if (i >= n4) return;
    float4 v = ((const float4*)in)[i];
    __nv_bfloat16 h0 = __float2bfloat16(v.x), h1 = __float2bfloat16(v.y);
    __nv_bfloat16 h2 = __float2bfloat16(v.z), h3 = __float2bfloat16(v.w);
    __nv_bfloat16 l0 = __float2bfloat16(v.x - __bfloat162float(h0));
    __nv_bfloat16 l1 = __float2bfloat16(v.y - __bfloat162float(h1));
    __nv_bfloat16 l2 = __float2bfloat16(v.z - __bfloat162float(h2));
    __nv_bfloat16 l3 = __float2bfloat16(v.w - __bfloat162float(h3));
    __nv_bfloat162 hp0(h0, h1), hp1(h2, h3), lp0(l0, l1), lp1(l2, l3);
    uint2 hv, lv;
    hv.x = *(uint32_t*)&hp0; hv.y = *(uint32_t*)&hp1;
    lv.x = *(uint32_t*)&lp0; lv.y = *(uint32_t*)&lp1;
    ((uint2*)hi)[i] = hv;
    ((uint2*)lo)[i] = lv;
}

// ---------------------------------------------------------------------------
// MMA helpers
// ---------------------------------------------------------------------------
__device__ __forceinline__ void mma_bf16(float* c, const uint32_t* a, const uint32_t* b)
{
    asm volatile(
        "mma.sync.aligned.m16n8k16.row.col.f32.bf16.bf16.f32 "
        "{%0,%1,%2,%3}, {%4,%5,%6,%7}, {%8,%9}, {%0,%1,%2,%3};"
        : "+f"(c[0]), "+f"(c[1]), "+f"(c[2]), "+f"(c[3])
        : "r"(a[0]), "r"(a[1]), "r"(a[2]), "r"(a[3]), "r"(b[0]), "r"(b[1]));
}

__device__ __forceinline__ void mma_tf32(float* c, const uint32_t* a,
                                         uint32_t b0, uint32_t b1)
{
    asm volatile(
        "mma.sync.aligned.m16n8k8.row.col.f32.tf32.tf32.f32 "
        "{%0,%1,%2,%3}, {%4,%5,%6,%7}, {%8,%9}, {%0,%1,%2,%3};"
        : "+f"(c[0]), "+f"(c[1]), "+f"(c[2]), "+f"(c[3])
        : "r"(a[0]), "r"(a[1]), "r"(a[2]), "r"(a[3]), "r"(b0), "r"(b1));
}

__device__ __forceinline__ uint32_t to_tf32(float f)
{
    uint32_t r;
    asm("cvt.rna.tf32.f32 %0, %1;" : "=r"(r) : "f"(f));
    return r;
}

__device__ __forceinline__ uint32_t pack_bf2(float a, float b)
{
    __nv_bfloat162 p(__float2bfloat16(a), __float2bfloat16(b));
    return *(uint32_t*)&p;
}

__device__ __forceinline__ void cpa16(uint32_t s, const void* g)
{
    asm volatile("cp.async.cg.shared.global [%0], [%1], 16;"
                 :: "r"(s), "l"(g) : "memory");
}

// ---------------------------------------------------------------------------
// GEMM v4 (unchanged from R15, passing): C = A @ B^T + bias, bf16 hi/lo x3.
// ---------------------------------------------------------------------------
#define SA_ROWB 144
#define ST_AH   0
#define ST_AL   (ST_AH + 128 * SA_ROWB)
#define ST_BH   (ST_AL + 128 * SA_ROWB)
#define ST_BL   (ST_BH + 64 * SA_ROWB)
#define STAGEB  (ST_BL + 64 * SA_ROWB)
#define GM_SMEM (2 * STAGEB)

__global__ __launch_bounds__(256, 2) void mma_gemm_kernel(
    const __nv_bfloat16* __restrict__ Ah, const __nv_bfloat16* __restrict__ Al,
    const __nv_bfloat16* __restrict__ Bh, const __nv_bfloat16* __restrict__ Bl,
    const float* __restrict__ bias, float* __restrict__ C, int Nc)
{
    extern __shared__ __align__(16) char sm[];
    const uint32_t sbase = (uint32_t)__cvta_generic_to_shared(sm);
    const int tid  = threadIdx.x;
    const int wid  = tid >> 5;
    const int lane = tid & 31;
    const int g    = lane >> 2;
    const int t4   = lane & 3;
    const int row0 = blockIdx.y * 128;
    const int col0 = blockIdx.x * 64;
    const int wm   = (wid & 3) * 32;
    const int wn   = (wid >> 2) * 32;

    auto load_chunk = [&](int it, int stg) {
        const uint32_t sb = sbase + stg * STAGEB;
        const int kb = it * 64;
#pragma unroll
        for (int i = 0; i < 4; i++) {
            int p = tid + (i << 8);
            int r = p >> 3, q = p & 7;
            size_t go = (size_t)(row0 + r) * 256 + kb + q * 8;
            uint32_t so = r * SA_ROWB + q * 16;
            cpa16(sb + ST_AH + so, Ah + go);
            cpa16(sb + ST_AL + so, Al + go);
        }
#pragma unroll
        for (int i = 0; i < 2; i++) {
            int p = tid + (i << 8);
            int r = p >> 3, q = p & 7;
            size_t go = (size_t)(col0 + r) * 256 + kb + q * 8;
            uint32_t so = r * SA_ROWB + q * 16;
            cpa16(sb + ST_BH + so, Bh + go);
            cpa16(sb + ST_BL + so, Bl + go);
        }
        asm volatile("cp.async.commit_group;" ::: "memory");
    };

    float acc[2][4][4];
#pragma unroll
    for (int mi = 0; mi < 2; mi++)
#pragma unroll
        for (int ni = 0; ni < 4; ni++)
#pragma unroll
            for (int k = 0; k < 4; k++) acc[mi][ni][k] = 0.f;

    const uint32_t a_row = (uint32_t)(wm + g);
    const uint32_t b_row = (uint32_t)(wn + g);
    const uint32_t kb0   = (uint32_t)(t4 * 4);

    load_chunk(0, 0);

#pragma unroll
    for (int it = 0; it < 4; it++) {
        if (it < 3) load_chunk(it + 1, (it + 1) & 1);
        if (it < 3) asm volatile("cp.async.wait_group 1;" ::: "memory");
        else        asm volatile("cp.async.wait_group 0;" ::: "memory");
        __syncthreads();

        const char* s = sm + (it & 1) * STAGEB;
#pragma unroll
        for (int p = 0; p < 3; p++) {
            const char* Ab = s + ((p == 2) ? ST_AL : ST_AH);
            const char* Bb = s + ((p == 1) ? ST_BL : ST_BH);
#pragma unroll
            for (int st = 0; st < 4; st++) {
                const uint32_t kf = (uint32_t)(st * 32) + kb0;
                uint32_t af[2][4], bf[4][2];
#pragma unroll
                for (int mi = 0; mi < 2; mi++) {
                    const char* ap = Ab + (a_row + mi * 16) * SA_ROWB + kf;
                    af[mi][0] = *(const uint32_t*)(ap);
                    af[mi][1] = *(const uint32_t*)(ap + 8 * SA_ROWB);
                    af[mi][2] = *(const uint32_t*)(ap + 16);
                    af[mi][3] = *(const uint32_t*)(ap + 8 * SA_ROWB + 16);
                }
#pragma unroll
                for (int ni = 0; ni < 4; ni++) {
                    const char* bp = Bb + (b_row + ni * 8) * SA_ROWB + kf;
                    bf[ni][0] = *(const uint32_t*)(bp);
                    bf[ni][1] = *(const uint32_t*)(bp + 16);
                }
#pragma unroll
                for (int mi = 0; mi < 2; mi++)
#pragma unroll
                    for (int ni = 0; ni < 4; ni++)
                        mma_bf16(acc[mi][ni], af[mi], bf[ni]);
            }
        }
        __syncthreads();
    }

#pragma unroll
    for (int mi = 0; mi < 2; mi++) {
        const int r0 = row0 + wm + mi * 16 + g;
#pragma unroll
        for (int ni = 0; ni < 4; ni++) {
            const int col = col0 + wn + ni * 8 + t4 * 2;
            const float bx = bias[col], by = bias[col + 1];
            float2 v0 = make_float2(acc[mi][ni][0] + bx, acc[mi][ni][1] + by);
            float2 v1 = make_float2(acc[mi][ni][2] + bx, acc[mi][ni][3] + by);
            *(float2*)(C + (size_t)r0 * Nc + col)       = v0;
            *(float2*)(C + (size_t)(r0 + 8) * Nc + col) = v1;
        }
    }
}

// ---------------------------------------------------------------------------
// HMMA flash attention. Block = (128 queries, 1 head), 4 warps x 32 rows.
// 32-key tiles. QK^T in tf32 (single pass), online softmax in fragments,
// P.V in bf16 hi/lo (3 passes, C-frag -> A-frag layout identity).
// K smem [key][36] u32(tf32); V smem transposed [dim][36] bf16 hi/lo.
// ---------------------------------------------------------------------------
#define MASKV (-3.0e38f)

__device__ __forceinline__ int lb_search(const int* __restrict__ a, int n, int v)
{
    int lo = 0, hi = n;
    while (lo < hi) {
        int mid = (lo + hi) >> 1;
        if (a[mid] < v) lo = mid + 1; else hi = mid;
    }
    return lo;
}

__global__ __launch_bounds__(128, 3) void attn_mma_kernel(
    const float* __restrict__ qkv, const int* __restrict__ bidx,
    __nv_bfloat16* __restrict__ oh, __nv_bfloat16* __restrict__ ol)
{
    __shared__ uint32_t      Ks[32 * 36];     // tf32 bits, [key][dim]
    __shared__ __nv_bfloat16 Vth[32 * 36];    // [dim][key]
    __shared__ __nv_bfloat16 Vtl[32 * 36];
    __shared__ int sh_range[2];

    const int h    = blockIdx.y;
    const int n0   = blockIdx.x * 128;
    const int tid  = threadIdx.x;
    const int wid  = tid >> 5;
    const int lane = tid & 31;
    const int g    = lane >> 2;
    const int t4   = lane & 3;
    const int wr   = n0 + wid * 32;

    // per-thread row segment ranges (rows: wr + mt*16 + sub*8 + g)
    int srow[2][2], erow[2][2];
#pragma unroll
    for (int mt = 0; mt < 2; mt++)
#pragma unroll
        for (int sub = 0; sub < 2; sub++) {
            int r = wr + mt * 16 + sub * 8 + g;
            int b = bidx[r];
            srow[mt][sub] = lb_search(bidx, NTOK, b);
            erow[mt][sub] = lb_search(bidx, NTOK, b + 1);
        }
    if (tid == 0)   sh_range[0] = srow[0][0];   // sorted: row n0 has min start
    if (tid == 127) sh_range[1] = erow[1][1];   // row n0+127 has max end

    // Q A-fragments (tf32), scale folded in
    const float scale = 0.1767766952966368811f;
    uint32_t qa[2][4][4];
#pragma unroll
    for (int mt = 0; mt < 2; mt++) {
        const float* qp = qkv + (size_t)(wr + mt * 16) * QKVDIM + h * HDIM;
#pragma unroll
        for (int ks = 0; ks < 4; ks++) {
            int d0 = ks * 8 + t4;
            qa[mt][ks][0] = to_tf32(qp[(size_t)g       * QKVDIM + d0    ] * scale);
            qa[mt][ks][1] = to_tf32(qp[(size_t)(g + 8) * QKVDIM + d0    ] * scale);
            qa[mt][ks][2] = to_tf32(qp[(size_t)g       * QKVDIM + d0 + 4] * scale);
            qa[mt][ks][3] = to_tf32(qp[(size_t)(g + 8) * QKVDIM + d0 + 4] * scale);
        }
    }

    float m[2][2] = {{-1e30f, -1e30f}, {-1e30f, -1e30f}};
    float l[2][2] = {{0.f, 0.f}, {0.f, 0.f}};
    float o[2][4][4];
#pragma unroll
    for (int mt = 0; mt < 2; mt++)
#pragma unroll
        for (int nh = 0; nh < 4; nh++)
#pragma unroll
            for (int c = 0; c < 4; c++) o[mt][nh][c] = 0.f;

    __syncthreads();
    const int smin = sh_range[0];
    const int emax = sh_range[1];

    for (int kt = smin; kt < emax; kt += 32) {
        // ---- load K (tf32) and V (bf16 hi/lo, transposed) tiles ----
#pragma unroll
        for (int i = 0; i < 2; i++) {
            int idx = tid + (i << 7);
            int r = idx >> 3, d4 = idx & 7;
            int kr = kt + r; if (kr > NTOK - 1) kr = NTOK - 1;
            const float* kp = qkv + (size_t)kr * QKVDIM + DMODEL + h * HDIM + d4 * 4;
            float4 kv = *(const float4*)kp;
            float4 vv = *(const float4*)(kp + DMODEL);
            uint4 kq;
            kq.x = to_tf32(kv.x); kq.y = to_tf32(kv.y);
            kq.z = to_tf32(kv.z); kq.w = to_tf32(kv.w);
            *(uint4*)&Ks[r * 36 + d4 * 4] = kq;
            float vj[4] = {vv.x, vv.y, vv.z, vv.w};
#pragma unroll
            for (int j = 0; j < 4; j++) {
                int d = d4 * 4 + j;
                __nv_bfloat16 vhi = __float2bfloat16(vj[j]);
                __nv_bfloat16 vlo = __float2bfloat16(vj[j] - __bfloat162float(vhi));
                Vth[d * 36 + r] = vhi;
                Vtl[d * 36 + r] = vlo;
            }
        }
        __syncthreads();

        // ---- S = Q K^T (tf32) ----
        float sc[2][4][4];
#pragma unroll
        for (int mt = 0; mt < 2; mt++)
#pragma unroll
            for (int nt = 0; nt < 4; nt++)
#pragma unroll
                for (int c = 0; c < 4; c++) sc[mt][nt][c] = 0.f;

#pragma unroll
        for (int nt = 0; nt < 4; nt++) {
            const uint32_t* kb = &Ks[(nt * 8 + g) * 36];
#pragma unroll
            for (int ks = 0; ks < 4; ks++) {
                uint32_t b0 = kb[ks * 8 + t4];
                uint32_t b1 = kb[ks * 8 + t4 + 4];
                mma_tf32(sc[0][nt], qa[0][ks], b0, b1);
                mma_tf32(sc[1][nt], qa[1][ks], b0, b1);
            }
        }

        // ---- mask + online softmax (row = quad of lanes) ----
#pragma unroll
        for (int mt = 0; mt < 2; mt++)
#pragma unroll
            for (int sub = 0; sub < 2; sub++) {
                const int s = srow[mt][sub], e = erow[mt][sub];
                float mx = MASKV;
#pragma unroll
                for (int nt = 0; nt < 4; nt++) {
                    int key0 = kt + nt * 8 + t4 * 2;
#pragma unroll
                    for (int c = 0; c < 2; c++) {
                        int key = key0 + c;
                        float v = sc[mt][nt][sub * 2 + c];
                        v = (key >= s && key < e) ? v : MASKV;
                        sc[mt][nt][sub * 2 + c] = v;
                        mx = fmaxf(mx, v);
                    }
                }
                mx = fmaxf(mx, __shfl_xor_sync(0xffffffffu, mx, 1));
                mx = fmaxf(mx, __shfl_xor_sync(0xffffffffu, mx, 2));
                float newm = fmaxf(m[mt][sub], mx);
                float corr = __expf(m[mt][sub] - newm);
                m[mt][sub] = newm;
                float lsum = 0.f;
#pragma unroll
                for (int nt = 0; nt < 4; nt++)
#pragma unroll
                    for (int c = 0; c < 2; c++) {
                        float p = __expf(sc[mt][nt][sub * 2 + c] - newm);
                        sc[mt][nt][sub * 2 + c] = p;
                        lsum += p;
                    }
                lsum += __shfl_xor_sync(0xffffffffu, lsum, 1);
                lsum += __shfl_xor_sync(0xffffffffu, lsum, 2);
                l[mt][sub] = l[mt][sub] * corr + lsum;
#pragma unroll
                for (int nh = 0; nh < 4; nh++) {
                    o[mt][nh][sub * 2]     *= corr;
                    o[mt][nh][sub * 2 + 1] *= corr;
                }
            }

        // ---- O += P V (bf16 hi/lo, 3 passes) ----
#pragma unroll
        for (int mt = 0; mt < 2; mt++) {
            uint32_t pah[2][4], pal[2][4];
#pragma unroll
            for (int kg = 0; kg < 2; kg++) {
                const float* pe = sc[mt][2 * kg];      // ntile 2kg
                const float* po = sc[mt][2 * kg + 1];  // ntile 2kg+1
                pah[kg][0] = pack_bf2(pe[0], pe[1]);
                pah[kg][1] = pack_bf2(pe[2], pe[3]);
                pah[kg][2] = pack_bf2(po[0], po[1]);
                pah[kg][3] = pack_bf2(po[2], po[3]);
                __nv_bfloat162 h0 = *(__nv_bfloat162*)&pah[kg][0];
                __nv_bfloat162 h1 = *(__nv_bfloat162*)&pah[kg][1];
                __nv_bfloat162 h2 = *(__nv_bfloat162*)&pah[kg][2];
                __nv_bfloat162 h3 = *(__nv_bfloat162*)&pah[kg][3];
                pal[kg][0] = pack_bf2(pe[0] - __bfloat162float(h0.x),
                                      pe[1] - __bfloat162float(h0.y));
                pal[kg][1] = pack_bf2(pe[2] - __bfloat162float(h1.x),
                                      pe[3] - __bfloat162float(h1.y));
                pal[kg][2] = pack_bf2(po[0] - __bfloat162float(h2.x),
                                      po[1] - __bfloat162float(h2.y));
                pal[kg][3] = pack_bf2(po[2] - __bfloat162float(h3.x),
                                      po[3] - __bfloat162float(h3.y));
            }
#pragma unroll
            for (int nh = 0; nh < 4; nh++) {
                const __nv_bfloat16* vh = &Vth[(nh * 8 + g) * 36];
                const __nv_bfloat16* vl = &Vtl[(nh * 8 + g) * 36];
#pragma unroll
                for (int kg = 0; kg < 2; kg++) {
                    uint32_t vb[2], vbl[2];
                    vb[0]  = *(const uint32_t*)(vh + kg * 16 + t4 * 2);
                    vb[1]  = *(const uint32_t*)(vh + kg * 16 + t4 * 2 + 8);
                    vbl[0] = *(const uint32_t*)(vl + kg * 16 + t4 * 2);
                    vbl[1] = *(const uint32_t*)(vl + kg * 16 + t4 * 2 + 8);
                    mma_bf16(o[mt][nh], pah[kg], vb);
                    mma_bf16(o[mt][nh], pah[kg], vbl);
                    mma_bf16(o[mt][nh], pal[kg], vb);
                }
            }
        }
        __syncthreads();   // tile consumed before next load overwrites
    }

    // ---- epilogue: normalize, split bf16 hi/lo, store ----
#pragma unroll
    for (int mt = 0; mt < 2; mt++)
#pragma unroll
        for (int sub = 0; sub < 2; sub++) {
            float inv = 1.f / l[mt][sub];
            int row = wr + mt * 16 + sub * 8 + g;
            size_t base = (size_t)row * DMODEL + h * HDIM;
#pragma unroll
            for (int nh = 0; nh < 4; nh++) {
                float v0 = o[mt][nh][sub * 2]     * inv;
                float v1 = o[mt][nh][sub * 2 + 1] * inv;
                __nv_bfloat16 h0 = __float2bfloat16(v0);
                __nv_bfloat16 h1 = __float2bfloat16(v1);
                uint32_t hp = pack_bf2(v0, v1);
                uint32_t lp = pack_bf2(v0 - __bfloat162float(h0),
                                       v1 - __bfloat162float(h1));
                *(uint32_t*)(oh + base + nh * 8 + t4 * 2) = hp;
                *(uint32_t*)(ol + base + nh * 8 + t4 * 2) = lp;
            }
        }
}

// ---------------------------------------------------------------------------
// Fused residual + LayerNorm. Warp per row.
// ---------------------------------------------------------------------------
__global__ __launch_bounds__(256) void ln_kernel(
    const float* __restrict__ x, const float* __restrict__ delta,
    const float* __restrict__ gamma, const float* __restrict__ beta,
    float* __restrict__ out)
{
    const int row  = blockIdx.x * 8 + (threadIdx.x >> 5);
    const int lane = threadIdx.x & 31;

    const float4* xp = (const float4*)(x + (size_t)row * DMODEL);
    const float4* dp = (const float4*)(delta + (size_t)row * DMODEL);

    float4 a = xp[lane],      bb = dp[lane];
    float4 v0 = make_float4(a.x + bb.x, a.y + bb.y, a.z + bb.z, a.w + bb.w);
    a = xp[lane + 32]; bb = dp[lane + 32];
    float4 v1 = make_float4(a.x + bb.x, a.y + bb.y, a.z + bb.z, a.w + bb.w);

    float sum = v0.x + v0.y + v0.z + v0.w + v1.x + v1.y + v1.z + v1.w;
#pragma unroll
    for (int off = 16; off; off >>= 1) sum += __shfl_xor_sync(0xffffffffu, sum, off);
    const float mean = sum * (1.f / 256.f);

    float sq = (v0.x - mean) * (v0.x - mean) + (v0.y - mean) * (v0.y - mean)
             + (v0.z - mean) * (v0.z - mean) + (v0.w - mean) * (v0.w - mean)
             + (v1.x - mean) * (v1.x - mean) + (v1.y - mean) * (v1.y - mean)
             + (v1.z - mean) * (v1.z - mean) + (v1.w - mean) * (v1.w - mean);
#pragma unroll
    for (int off = 16; off; off >>= 1) sq += __shfl_xor_sync(0xffffffffu, sq, off);
    const float rstd = rsqrtf(sq * (1.f / 256.f) + 1e-5f);

    float4 g = ((const float4*)gamma)[lane];
    float4 bt = ((const float4*)beta)[lane];
    float4 r0;
    r0.x = (v0.x - mean) * rstd * g.x + bt.x;
    r0.y = (v0.y - mean) * rstd * g.y + bt.y;
    r0.z = (v0.z - mean) * rstd * g.z + bt.z;
    r0.w = (v0.w - mean) * rstd * g.w + bt.w;
    g  = ((const float4*)gamma)[lane + 32];
    bt = ((const float4*)beta)[lane + 32];
    float4 r1;
    r1.x = (v1.x - mean) * rstd * g.x + bt.x;
    r1.y = (v1.y - mean) * rstd * g.y + bt.y;
    r1.z = (v1.z - mean) * rstd * g.z + bt.z;
    r1.w = (v1.w - mean) * rstd * g.w + bt.w;

    float4* op = (float4*)(out + (size_t)row * DMODEL);
    op[lane]      = r0;
    op[lane + 32] = r1;
}

// ---------------------------------------------------------------------------
// Launch (graph-capturable: kernel launches on default stream only)
// ---------------------------------------------------------------------------
extern "C" void kernel_launch(void* const* d_in, const int* in_sizes, int n_in,
                              void* d_out, int out_size)
{
    const float* slots  = (const float*)d_in[0];   // [1, 4096, 256]
    const int*   bidx   = (const int*)  d_in[1];   // [4096] sorted
    const float* w_in   = (const float*)d_in[2];   // [768, 256]
    const float* b_in   = (const float*)d_in[3];   // [768]
    const float* w_out  = (const float*)d_in[4];   // [256, 256]
    const float* b_out  = (const float*)d_in[5];   // [256]
    const float* ln_g   = (const float*)d_in[6];   // [256]
    const float* ln_b   = (const float*)d_in[7];   // [256]
    float*       out    = (float*)d_out;           // [1, 4096, 256]

    float *qkv, *delta;
    __nv_bfloat16 *xh, *xl, *wih, *wil, *woh, *wol, *ah, *al;
    cudaGetSymbolAddress((void**)&qkv,   g_qkv);
    cudaGetSymbolAddress((void**)&delta, g_delta);
    cudaGetSymbolAddress((void**)&xh,  g_xh);
    cudaGetSymbolAddress((void**)&xl,  g_xl);
    cudaGetSymbolAddress((void**)&wih, g_wih);
    cudaGetSymbolAddress((void**)&wil, g_wil);
    cudaGetSymbolAddress((void**)&woh, g_woh);
    cudaGetSymbolAddress((void**)&wol, g_wol);
    cudaGetSymbolAddress((void**)&ah,  g_ah);
    cudaGetSymbolAddress((void**)&al,  g_al);

    cudaFuncSetAttribute(mma_gemm_kernel,
                         cudaFuncAttributeMaxDynamicSharedMemorySize, GM_SMEM);

    // 0) one-time fp32 -> bf16 hi/lo splits
    split_bf16_kernel<<<NTOK * DMODEL / 4 / 256, 256>>>(slots, xh, xl, NTOK * DMODEL / 4);
    split_bf16_kernel<<<QKVDIM * DMODEL / 4 / 256, 256>>>(w_in, wih, wil, QKVDIM * DMODEL / 4);
    split_bf16_kernel<<<DMODEL * DMODEL / 4 / 256, 256>>>(w_out, woh, wol, DMODEL * DMODEL / 4);

    // 1) QKV = x @ w_in^T + b_in   [4096, 768]
    {
        dim3 grid(QKVDIM / 64, NTOK / 128);
        mma_gemm_kernel<<<grid, 256, GM_SMEM>>>(xh, xl, wih, wil, b_in, qkv, QKVDIM);
    }
    // 2) Block-diagonal attention (HMMA) -> bf16 hi/lo   [4096, 256]
    {
        dim3 grid(NTOK / 128, NHEAD);
        attn_mma_kernel<<<grid, 128>>>(qkv, bidx, ah, al);
    }
    // 3) delta = attn @ w_out^T + b_out   [4096, 256]
    {
        dim3 grid(DMODEL / 64, NTOK / 128);
        mma_gemm_kernel<<<grid, 256, GM_SMEM>>>(ah, al, woh, wol, b_out, delta, DMODEL);
    }
    // 4) out = LayerNorm(x + delta)
    ln_kernel<<<NTOK / 8, 256>>>(slots, delta, ln_g, ln_b, out);
}